// round 4
// baseline (speedup 1.0000x reference)
#include <cuda_runtime.h>
#include <cuda_bf16.h>
#include <math.h>

// ---------------------------------------------------------------------------
// Problem constants
// ---------------------------------------------------------------------------
#define BB    4          // batch
#define BPTT  16
#define PRED  4
#define SS    20         // S = BPTT + PRED
#define VV    512        // 8*8*8 voxels
#define EE    256
#define NHH   8
#define HEADD 32
#define HIDD  512
#define NEE   512
#define FF    80         // B * S frames

#define FVE   ((size_t)FF * VV * EE)    // 10,485,760
#define FVH   ((size_t)FF * VV * HIDD)  // 20,971,520
#define SCORE_SIZE (BB * NEE * PRED * VV)  // 4,194,304
#define NROWS (BB * PRED * VV)             // 8192

// ---------------------------------------------------------------------------
// Scratch (allocation-free: __device__ globals)
// ---------------------------------------------------------------------------
__device__ float g_x[FVE];
__device__ float g_h[FVE];
__device__ float g_q[FVE];
__device__ float g_k[FVE];
__device__ float g_v[FVE];
__device__ float g_ao[FVE];
__device__ float g_hid[FVH];
__device__ float g_logits[FVH];
__device__ float g_rowloss[NROWS];

// ---------------------------------------------------------------------------
// Embedding: x[b,s,v,e] = emb[tok][e] + pos[s][e]
// ---------------------------------------------------------------------------
__global__ void embed_kernel(const int* __restrict__ code,
                             const float* __restrict__ emb,
                             const float* __restrict__ pos,
                             float* __restrict__ x)
{
    size_t idx = (size_t)blockIdx.x * blockDim.x + threadIdx.x;
    if (idx >= FVE) return;
    int e = (int)(idx & 255);
    int v = (int)((idx >> 8) & 511);
    int f = (int)(idx >> 17);            // /(256*512)
    int b = f / SS, s = f % SS;
    int tok = (s < BPTT) ? code[((b * BPTT + s) << 9) + v] : NEE;
    x[idx] = emb[tok * EE + e] + pos[s * EE + e];
}

// ---------------------------------------------------------------------------
// LayerNorm over last dim (E=256), warp per row
// ---------------------------------------------------------------------------
__global__ void ln_kernel(const float* __restrict__ in, float* __restrict__ out,
                          const float* __restrict__ sc, const float* __restrict__ bi,
                          int rows)
{
    int wid  = (int)((blockIdx.x * blockDim.x + threadIdx.x) >> 5);
    int lane = threadIdx.x & 31;
    if (wid >= rows) return;
    const float* p = in + (size_t)wid * EE;
    float v8[8];
    float s = 0.f, sq = 0.f;
#pragma unroll
    for (int i = 0; i < 8; ++i) {
        float xv = p[lane + i * 32];
        v8[i] = xv;
        s += xv;
        sq = fmaf(xv, xv, sq);
    }
#pragma unroll
    for (int off = 16; off > 0; off >>= 1) {
        s  += __shfl_xor_sync(0xffffffffu, s, off);
        sq += __shfl_xor_sync(0xffffffffu, sq, off);
    }
    float m   = s * (1.f / 256.f);
    float var = sq * (1.f / 256.f) - m * m;
    if (var < 0.f) var = 0.f;
    float inv = rsqrtf(var + 1e-5f);
    float* q = out + (size_t)wid * EE;
#pragma unroll
    for (int i = 0; i < 8; ++i) {
        int e = lane + i * 32;
        q[e] = (v8[i] - m) * inv * sc[e] + bi[e];
    }
}

// ---------------------------------------------------------------------------
// 3D conv, 3x3x3, SAME padding, implicit GEMM.
//   x: [F][512][Cin]   w: [27][Cin][Cout]   y: [F][512][Cout]
// Block: one frame f, one 64-wide cout tile, one 2-slice z quarter.
// SMEM: padded activation chunk xs[8ch][4z * 10y * 10x] + weight chunk
// ws[27][8ch][64co]. Thread: 8 voxels (one x-row) x 8 couts accumulators.
// ---------------------------------------------------------------------------
#define CONV_SMEM_FLOATS (8 * 400 + 27 * 8 * 64)   // 3200 + 13824 = 17024
#define CONV_SMEM_BYTES  (CONV_SMEM_FLOATS * 4)    // 68096

__global__ void __launch_bounds__(128)
conv3d_kernel(const float* __restrict__ x, const float* __restrict__ w,
              const float* __restrict__ bias, const float* __restrict__ residual,
              float* __restrict__ y, int Cin, int Cout, int do_gelu)
{
    extern __shared__ float smem[];
    float* xs = smem;            // [8][400]
    float* ws = smem + 3200;     // [27][8][64]

    const int t     = threadIdx.x;
    const int f     = blockIdx.x;
    const int co0   = blockIdx.y * 64;
    const int zbase = blockIdx.z * 2;

    const int cg = t & 7;        // cout octet within tile
    const int g  = t >> 3;       // 0..15 : (zl, y)
    const int zl = g >> 3;       // 0..1
    const int gy = g & 7;
    const int pbase = (zl + 1) * 100 + (gy + 1) * 10 + 1;

    for (int i = t; i < 3200; i += 128) xs[i] = 0.f;

    float acc[8][8];
#pragma unroll
    for (int j = 0; j < 8; ++j)
#pragma unroll
        for (int c = 0; c < 8; ++c) acc[j][c] = 0.f;

    const float* xf = x + (size_t)f * VV * Cin;
    const int nch = Cin >> 3;

    for (int kc = 0; kc < nch; ++kc) {
        __syncthreads();
        // ---- fill activation chunk (4 z-slices incl halo, 8x8 each, 8 ch)
#pragma unroll
        for (int rep = 0; rep < 2; ++rep) {
            int j  = t + rep * 128;      // 0..255
            int lz = j >> 6;             // 0..3  (pz directly)
            int vy = (j >> 3) & 7;
            int vx = j & 7;
            int gz = zbase + lz - 1;
            float val[8];
            if ((unsigned)gz < 8u) {
                const float4* src = (const float4*)(xf + (size_t)(gz * 64 + vy * 8 + vx) * Cin + kc * 8);
                float4 r0 = src[0], r1 = src[1];
                val[0] = r0.x; val[1] = r0.y; val[2] = r0.z; val[3] = r0.w;
                val[4] = r1.x; val[5] = r1.y; val[6] = r1.z; val[7] = r1.w;
            } else {
#pragma unroll
                for (int kk = 0; kk < 8; ++kk) val[kk] = 0.f;
            }
            int p = lz * 100 + (vy + 1) * 10 + (vx + 1);
#pragma unroll
            for (int kk = 0; kk < 8; ++kk) xs[kk * 400 + p] = val[kk];
        }
        // ---- fill weight chunk: 27*8*64 floats = 3456 float4
        {
            float4* wd = (float4*)ws;
            for (int i = t; i < 3456; i += 128) {
                int o  = i >> 7;         // /128 (128 float4 per tap)
                int r  = i & 127;
                int kk = r >> 4;         // /16  (16 float4 per cin)
                int c4 = r & 15;
                wd[i] = *(const float4*)&w[((size_t)o * Cin + (kc * 8 + kk)) * Cout + co0 + c4 * 4];
            }
        }
        __syncthreads();

        const float4* ws4 = (const float4*)ws;
#pragma unroll 1
        for (int o = 0; o < 27; ++o) {
            int dz = o / 9 - 1;
            int rr = o % 9;
            int dy = rr / 3 - 1;
            int dx = rr % 3 - 1;
            const float* xo = xs + pbase + dz * 100 + dy * 10 + dx;
#pragma unroll
            for (int kk = 0; kk < 8; ++kk) {
                const float* xp = xo + kk * 400;
                float aa[8];
#pragma unroll
                for (int j = 0; j < 8; ++j) aa[j] = xp[j];
                float4 b0 = ws4[(o * 8 + kk) * 16 + cg * 2];
                float4 b1 = ws4[(o * 8 + kk) * 16 + cg * 2 + 1];
                float bbv[8] = {b0.x, b0.y, b0.z, b0.w, b1.x, b1.y, b1.z, b1.w};
#pragma unroll
                for (int j = 0; j < 8; ++j)
#pragma unroll
                    for (int c = 0; c < 8; ++c)
                        acc[j][c] = fmaf(aa[j], bbv[c], acc[j][c]);
            }
        }
    }

    // ---- epilogue: bias (+residual) (+gelu)
    int co = co0 + cg * 8;
    float bv[8];
#pragma unroll
    for (int c = 0; c < 8; ++c) bv[c] = bias[co + c];
#pragma unroll
    for (int j = 0; j < 8; ++j) {
        int vox = (zbase + zl) * 64 + gy * 8 + j;
        size_t oi = ((size_t)f * VV + vox) * Cout + co;
        float r[8];
#pragma unroll
        for (int c = 0; c < 8; ++c) r[c] = acc[j][c] + bv[c];
        if (residual) {
            const float4* rp = (const float4*)(residual + oi);
            float4 r0 = rp[0], r1 = rp[1];
            r[0] += r0.x; r[1] += r0.y; r[2] += r0.z; r[3] += r0.w;
            r[4] += r1.x; r[5] += r1.y; r[6] += r1.z; r[7] += r1.w;
        }
        if (do_gelu) {
#pragma unroll
            for (int c = 0; c < 8; ++c)
                r[c] = 0.5f * r[c] * (1.f + erff(r[c] * 0.7071067811865475f));
        }
        float4* op = (float4*)(y + oi);
        op[0] = make_float4(r[0], r[1], r[2], r[3]);
        op[1] = make_float4(r[4], r[5], r[6], r[7]);
    }
}

// ---------------------------------------------------------------------------
// Attention over time (20 steps) per (b, voxel, head). One warp per unit.
// ---------------------------------------------------------------------------
__global__ void __launch_bounds__(128)
attn_kernel(const float* __restrict__ q, const float* __restrict__ k,
            const float* __restrict__ v, float* __restrict__ o)
{
    __shared__ float sm[4][2380];   // per warp: q 20x33, k 20x33, v 20x33, at 20x20
    int wlocal = threadIdx.x >> 5;
    int lane   = threadIdx.x & 31;
    int wid    = blockIdx.x * 4 + wlocal;     // 0..16383 (B*V*NH)
    int h  = wid & 7;
    int vx = (wid >> 3) & 511;
    int b  = wid >> 12;

    float* qs = sm[wlocal];
    float* ks = qs + 660;
    float* vs = ks + 660;
    float* at = vs + 660;

    size_t base = (size_t)vx * EE + h * HEADD + lane;
#pragma unroll
    for (int s = 0; s < SS; ++s) {
        size_t gi = (size_t)(b * SS + s) * (VV * EE) + base;
        qs[s * 33 + lane] = q[gi];
        ks[s * 33 + lane] = k[gi];
        vs[s * 33 + lane] = v[gi];
    }
    __syncwarp();

    const float scale = 0.17677669529663687f;  // 1/sqrt(32)
    int tt = lane;
#pragma unroll 1
    for (int s = 0; s < SS; ++s) {
        float sc = -1e30f;
        if (tt < SS) {
            float a = 0.f;
#pragma unroll
            for (int d = 0; d < HEADD; ++d)
                a = fmaf(qs[s * 33 + d], ks[tt * 33 + d], a);
            sc = a * scale;
        }
        float m = sc;
#pragma unroll
        for (int off = 16; off > 0; off >>= 1)
            m = fmaxf(m, __shfl_xor_sync(0xffffffffu, m, off));
        float e = (tt < SS) ? expf(sc - m) : 0.f;
        float su = e;
#pragma unroll
        for (int off = 16; off > 0; off >>= 1)
            su += __shfl_xor_sync(0xffffffffu, su, off);
        if (tt < SS) at[s * SS + tt] = e / su;
    }
    __syncwarp();

#pragma unroll 1
    for (int s = 0; s < SS; ++s) {
        float a = 0.f;
#pragma unroll
        for (int t2 = 0; t2 < SS; ++t2)
            a = fmaf(at[s * SS + t2], vs[t2 * 33 + lane], a);
        o[(size_t)(b * SS + s) * (VV * EE) + base] = a;
    }
}

// ---------------------------------------------------------------------------
// Final linear: [40960 x 256] @ [256 x 512] + bias -> logits
// ---------------------------------------------------------------------------
__global__ void __launch_bounds__(256)
linear_kernel(const float* __restrict__ A, const float* __restrict__ Bw,
              const float* __restrict__ bias, float* __restrict__ C)
{
    __shared__ float As[32 * 65];
    __shared__ float Bs[32 * 64];
    int t  = threadIdx.x;
    int tx = t & 15, ty = t >> 4;
    int m0 = blockIdx.x * 64, n0 = blockIdx.y * 64;
    float acc[4][4];
#pragma unroll
    for (int i = 0; i < 4; ++i)
#pragma unroll
        for (int j = 0; j < 4; ++j) acc[i][j] = 0.f;

    for (int kt = 0; kt < 8; ++kt) {
        for (int i = t; i < 2048; i += 256) {
            int r = i >> 5, kk = i & 31;
            As[kk * 65 + r] = A[(size_t)(m0 + r) * EE + kt * 32 + kk];
        }
        for (int i = t; i < 2048; i += 256) {
            int kk = i >> 6, c = i & 63;
            Bs[kk * 64 + c] = Bw[(size_t)(kt * 32 + kk) * NEE + n0 + c];
        }
        __syncthreads();
#pragma unroll
        for (int kk = 0; kk < 32; ++kk) {
            float a[4];
#pragma unroll
            for (int i = 0; i < 4; ++i) a[i] = As[kk * 65 + ty * 4 + i];
            float4 bvv = *(const float4*)&Bs[kk * 64 + tx * 4];
            float bvals[4] = {bvv.x, bvv.y, bvv.z, bvv.w};
#pragma unroll
            for (int i = 0; i < 4; ++i)
#pragma unroll
                for (int j = 0; j < 4; ++j)
                    acc[i][j] = fmaf(a[i], bvals[j], acc[i][j]);
        }
        __syncthreads();
    }
#pragma unroll
    for (int i = 0; i < 4; ++i)
#pragma unroll
        for (int j = 0; j < 4; ++j)
            C[(size_t)(m0 + ty * 4 + i) * NEE + n0 + tx * 4 + j] =
                acc[i][j] + bias[n0 + tx * 4 + j];
}

// ---------------------------------------------------------------------------
// Score transpose: score[b][c][p][v] = logits[b*20+16+p][v][c]
// ---------------------------------------------------------------------------
__global__ void score_kernel(const float* __restrict__ logits, float* __restrict__ out,
                             int out_size)
{
    __shared__ float tile[32][33];
    int bp = blockIdx.z;
    int b = bp >> 2, p = bp & 3;
    int v0 = blockIdx.x * 32, c0 = blockIdx.y * 32;
    int f = b * SS + BPTT + p;
    int t = threadIdx.x;
    int ci = t & 31, vi = t >> 5;     // vi 0..7
#pragma unroll
    for (int r = 0; r < 32; r += 8)
        tile[vi + r][ci] = logits[((size_t)f * VV + v0 + vi + r) * NEE + c0 + ci];
    __syncthreads();
    int vv2 = t & 31, cc = t >> 5;
#pragma unroll
    for (int r = 0; r < 32; r += 8) {
        size_t oidx = (((size_t)(b * NEE + c0 + cc + r)) * PRED + p) * VV + v0 + vv2;
        if (oidx < (size_t)out_size) out[oidx] = tile[vv2][cc + r];
    }
}

// ---------------------------------------------------------------------------
// Per-row log-softmax target loss + argmax. Warp per (b,p,v) row.
// ---------------------------------------------------------------------------
__global__ void loss_argmax_kernel(const float* __restrict__ logits,
                                   const int* __restrict__ ncode,
                                   float* __restrict__ rowloss,
                                   float* __restrict__ out, int write_code)
{
    int wid  = (int)((blockIdx.x * blockDim.x + threadIdx.x) >> 5);
    int lane = threadIdx.x & 31;
    if (wid >= NROWS) return;
    int v = wid & 511, p = (wid >> 9) & 3, b = wid >> 11;
    const float* lp = logits + ((size_t)(b * SS + BPTT + p) * VV + v) * NEE;

    float vals[16];
    float mx = -1e30f;
    int mi = 0;
#pragma unroll
    for (int i = 0; i < 16; ++i) {
        int c = lane + i * 32;
        float xv = lp[c];
        vals[i] = xv;
        if (xv > mx) { mx = xv; mi = c; }
    }
#pragma unroll
    for (int off = 16; off > 0; off >>= 1) {
        float om = __shfl_xor_sync(0xffffffffu, mx, off);
        int   oi = __shfl_xor_sync(0xffffffffu, mi, off);
        if (om > mx || (om == mx && oi < mi)) { mx = om; mi = oi; }
    }
    float se = 0.f;
#pragma unroll
    for (int i = 0; i < 16; ++i) se += expf(vals[i] - mx);
#pragma unroll
    for (int off = 16; off > 0; off >>= 1)
        se += __shfl_xor_sync(0xffffffffu, se, off);

    int tgt = ncode[wid];
    if (lane == (tgt & 31))
        rowloss[wid] = -(vals[tgt >> 5] - mx - logf(se));
    if (write_code && lane == 0)
        out[(size_t)SCORE_SIZE + 1 + wid] = (float)mi;
}

__global__ void loss_reduce_kernel(const float* __restrict__ rowloss,
                                   float* __restrict__ out, int loss_off)
{
    __shared__ float smr[256];
    int t = threadIdx.x;
    float a = 0.f;
    for (int i = t; i < NROWS; i += 256) a += rowloss[i];
    smr[t] = a;
    __syncthreads();
    for (int s = 128; s > 0; s >>= 1) {
        if (t < s) smr[t] += smr[t + s];
        __syncthreads();
    }
    if (t == 0) out[loss_off] = smr[0] * (1.f / (float)NROWS);
}

// ---------------------------------------------------------------------------
// Orchestration
// ---------------------------------------------------------------------------
extern "C" void kernel_launch(void* const* d_in, const int* in_sizes, int n_in,
                              void* d_out, int out_size)
{
    (void)in_sizes; (void)n_in;
    const int*   code   = (const int*)  d_in[0];
    const int*   ncode  = (const int*)  d_in[1];
    const float* emb    = (const float*)d_in[2];
    const float* pos    = (const float*)d_in[3];
    const float* ln1s   = (const float*)d_in[4];
    const float* ln1b   = (const float*)d_in[5];
    const float* ln2s   = (const float*)d_in[6];
    const float* ln2b   = (const float*)d_in[7];
    const float* wq     = (const float*)d_in[8];
    const float* bq     = (const float*)d_in[9];
    const float* wk     = (const float*)d_in[10];
    const float* bk     = (const float*)d_in[11];
    const float* wv     = (const float*)d_in[12];
    const float* bv     = (const float*)d_in[13];
    const float* wo     = (const float*)d_in[14];
    const float* bo     = (const float*)d_in[15];
    const float* w1     = (const float*)d_in[16];
    const float* b1     = (const float*)d_in[17];
    const float* w2     = (const float*)d_in[18];
    const float* b2     = (const float*)d_in[19];
    const float* lnfs   = (const float*)d_in[20];
    const float* lnfb   = (const float*)d_in[21];
    const float* decw   = (const float*)d_in[22];
    const float* decb   = (const float*)d_in[23];
    const float* declns = (const float*)d_in[24];
    const float* declnb = (const float*)d_in[25];
    const float* linw   = (const float*)d_in[26];
    const float* linb   = (const float*)d_in[27];
    float* out = (float*)d_out;

    float *px, *ph, *pq, *pk, *pv, *pa, *phid, *plog, *prl;
    cudaGetSymbolAddress((void**)&px,   g_x);
    cudaGetSymbolAddress((void**)&ph,   g_h);
    cudaGetSymbolAddress((void**)&pq,   g_q);
    cudaGetSymbolAddress((void**)&pk,   g_k);
    cudaGetSymbolAddress((void**)&pv,   g_v);
    cudaGetSymbolAddress((void**)&pa,   g_ao);
    cudaGetSymbolAddress((void**)&phid, g_hid);
    cudaGetSymbolAddress((void**)&plog, g_logits);
    cudaGetSymbolAddress((void**)&prl,  g_rowloss);

    cudaFuncSetAttribute(conv3d_kernel,
                         cudaFuncAttributeMaxDynamicSharedMemorySize,
                         CONV_SMEM_BYTES);

    const int ROWS = FF * VV;                  // 40960
    const int LN_BLOCKS = (ROWS * 32) / 256;   // 5120
    const size_t WEE = 27 * 256 * 256;         // per-layer E->E weight stride
    const size_t WEH = 27 * 256 * 512;         // per-layer E->HID (== HID->E)

    embed_kernel<<<(int)((FVE + 255) / 256), 256>>>(code, emb, pos, px);

    dim3 cgE(FF, 4, 4);   // Cout=256
    dim3 cgH(FF, 8, 4);   // Cout=512
    for (int i = 0; i < 4; ++i) {
        ln_kernel<<<LN_BLOCKS, 256>>>(px, ph, ln1s + i * EE, ln1b + i * EE, ROWS);
        conv3d_kernel<<<cgE, 128, CONV_SMEM_BYTES>>>(ph, wq + i * WEE, bq + i * EE, nullptr, pq, 256, 256, 0);
        conv3d_kernel<<<cgE, 128, CONV_SMEM_BYTES>>>(ph, wk + i * WEE, bk + i * EE, nullptr, pk, 256, 256, 0);
        conv3d_kernel<<<cgE, 128, CONV_SMEM_BYTES>>>(ph, wv + i * WEE, bv + i * EE, nullptr, pv, 256, 256, 0);
        attn_kernel<<<4096, 128>>>(pq, pk, pv, pa);
        conv3d_kernel<<<cgE, 128, CONV_SMEM_BYTES>>>(pa, wo + i * WEE, bo + i * EE, px, px, 256, 256, 0);
        ln_kernel<<<LN_BLOCKS, 256>>>(px, ph, ln2s + i * EE, ln2b + i * EE, ROWS);
        conv3d_kernel<<<cgH, 128, CONV_SMEM_BYTES>>>(ph, w1 + i * WEH, b1 + i * HIDD, nullptr, phid, 256, 512, 1);
        conv3d_kernel<<<cgE, 128, CONV_SMEM_BYTES>>>(phid, w2 + i * WEH, b2 + i * EE, px, px, 512, 256, 0);
    }

    ln_kernel<<<LN_BLOCKS, 256>>>(px, ph, lnfs, lnfb, ROWS);
    conv3d_kernel<<<cgE, 128, CONV_SMEM_BYTES>>>(ph, decw, decb, nullptr, pq, 256, 256, 1);
    ln_kernel<<<LN_BLOCKS, 256>>>(pq, pk, declns, declnb, ROWS);
    linear_kernel<<<dim3(ROWS / 64, NEE / 64), 256>>>(pk, linw, linb, plog);

    if (out_size >= SCORE_SIZE) {
        dim3 sg(16, 16, 16);
        score_kernel<<<sg, 256>>>(plog, out, out_size);
    }
    int write_code = (out_size >= SCORE_SIZE + 1 + NROWS) ? 1 : 0;
    loss_argmax_kernel<<<(NROWS * 32) / 256, 256>>>(plog, ncode, prl, out, write_code);

    int loss_off = -1;
    if (out_size == 1) loss_off = 0;
    else if (out_size > SCORE_SIZE) loss_off = SCORE_SIZE;
    if (loss_off >= 0)
        loss_reduce_kernel<<<1, 256>>>(prl, out, loss_off);
}

// round 5
// speedup vs baseline: 1.1489x; 1.1489x over previous
#include <cuda_runtime.h>
#include <cuda_bf16.h>
#include <math.h>

// ---------------------------------------------------------------------------
// Problem constants
// ---------------------------------------------------------------------------
#define BB    4          // batch
#define BPTT  16
#define PRED  4
#define SS    20         // S = BPTT + PRED
#define VV    512        // 8*8*8 voxels
#define EE    256
#define NHH   8
#define HEADD 32
#define HIDD  512
#define NEE   512
#define FF    80         // B * S frames

#define FVE   ((size_t)FF * VV * EE)    // 10,485,760
#define FVH   ((size_t)FF * VV * HIDD)  // 20,971,520
#define SCORE_SIZE (BB * NEE * PRED * VV)  // 4,194,304
#define NROWS (BB * PRED * VV)             // 8192

// ---------------------------------------------------------------------------
// Scratch (allocation-free: __device__ globals)
// ---------------------------------------------------------------------------
__device__ float g_x[FVE];
__device__ float g_h[FVE];
__device__ float g_q[FVE];
__device__ float g_k[FVE];
__device__ float g_v[FVE];
__device__ float g_ao[FVE];
__device__ float g_hid[FVH];
__device__ float g_logits[FVH];
__device__ float g_rowloss[NROWS];

// ---------------------------------------------------------------------------
// Packed fp32x2 helpers (sm_100+). Numerically identical to 2x scalar FFMA.
// ---------------------------------------------------------------------------
__device__ __forceinline__ unsigned long long dup_f32x2(float x) {
    unsigned long long r;
    asm("mov.b64 %0, {%1, %1};" : "=l"(r) : "f"(x));
    return r;
}
__device__ __forceinline__ void fma_f32x2(unsigned long long& acc,
                                          unsigned long long a,
                                          unsigned long long b) {
    asm("fma.rn.f32x2 %0, %1, %2, %0;" : "+l"(acc) : "l"(a), "l"(b));
}
__device__ __forceinline__ void unpack_f32x2(unsigned long long p, float& lo, float& hi) {
    asm("mov.b64 {%0, %1}, %2;" : "=f"(lo), "=f"(hi) : "l"(p));
}
union F4U2 { float4 f; unsigned long long u[2]; };

// ---------------------------------------------------------------------------
// Embedding: x[b,s,v,e] = emb[tok][e] + pos[s][e]
// ---------------------------------------------------------------------------
__global__ void embed_kernel(const int* __restrict__ code,
                             const float* __restrict__ emb,
                             const float* __restrict__ pos,
                             float* __restrict__ x)
{
    size_t idx = (size_t)blockIdx.x * blockDim.x + threadIdx.x;
    if (idx >= FVE) return;
    int e = (int)(idx & 255);
    int v = (int)((idx >> 8) & 511);
    int f = (int)(idx >> 17);            // /(256*512)
    int b = f / SS, s = f % SS;
    int tok = (s < BPTT) ? code[((b * BPTT + s) << 9) + v] : NEE;
    x[idx] = emb[tok * EE + e] + pos[s * EE + e];
}

// ---------------------------------------------------------------------------
// LayerNorm over last dim (E=256), warp per row
// ---------------------------------------------------------------------------
__global__ void ln_kernel(const float* __restrict__ in, float* __restrict__ out,
                          const float* __restrict__ sc, const float* __restrict__ bi,
                          int rows)
{
    int wid  = (int)((blockIdx.x * blockDim.x + threadIdx.x) >> 5);
    int lane = threadIdx.x & 31;
    if (wid >= rows) return;
    const float* p = in + (size_t)wid * EE;
    float v8[8];
    float s = 0.f, sq = 0.f;
#pragma unroll
    for (int i = 0; i < 8; ++i) {
        float xv = p[lane + i * 32];
        v8[i] = xv;
        s += xv;
        sq = fmaf(xv, xv, sq);
    }
#pragma unroll
    for (int off = 16; off > 0; off >>= 1) {
        s  += __shfl_xor_sync(0xffffffffu, s, off);
        sq += __shfl_xor_sync(0xffffffffu, sq, off);
    }
    float m   = s * (1.f / 256.f);
    float var = sq * (1.f / 256.f) - m * m;
    if (var < 0.f) var = 0.f;
    float inv = rsqrtf(var + 1e-5f);
    float* q = out + (size_t)wid * EE;
#pragma unroll
    for (int i = 0; i < 8; ++i) {
        int e = lane + i * 32;
        q[e] = (v8[i] - m) * inv * sc[e] + bi[e];
    }
}

// ---------------------------------------------------------------------------
// 3D conv, 3x3x3, SAME padding, implicit GEMM.
//   x: [F][512][Cin]   w: [27][Cin][Cout]   y: [F][512][Cout]
// Block: one frame f, one 64-wide cout tile, one 2-slice z quarter.
// SMEM: padded activation chunk xs[8ch][4z * 10y * 10x] + weight chunk
// ws[27][8ch][64co]. Thread: 8 voxels (one x-row) x 8 couts (4 f32x2 pairs).
// Mainloop: per (cin, dz, dy) load the 10-wide halo row into registers ONCE,
// then the 3 dx taps hit registers; FMAs are packed fma.rn.f32x2.
// ---------------------------------------------------------------------------
#define CONV_SMEM_FLOATS (8 * 400 + 27 * 8 * 64)   // 3200 + 13824 = 17024
#define CONV_SMEM_BYTES  (CONV_SMEM_FLOATS * 4)    // 68096

__global__ void __launch_bounds__(128)
conv3d_kernel(const float* __restrict__ x, const float* __restrict__ w,
              const float* __restrict__ bias, const float* __restrict__ residual,
              float* __restrict__ y, int Cin, int Cout, int do_gelu)
{
    extern __shared__ float smem[];
    float* xs = smem;            // [8][400]
    float* ws = smem + 3200;     // [27][8][64]

    const int t     = threadIdx.x;
    const int f     = blockIdx.x;
    const int co0   = blockIdx.y * 64;
    const int zbase = blockIdx.z * 2;

    const int cg = t & 7;        // cout octet within tile
    const int g  = t >> 3;       // 0..15 : (zl, y)
    const int zl = g >> 3;       // 0..1
    const int gy = g & 7;

    for (int i = t; i < 3200; i += 128) xs[i] = 0.f;

    unsigned long long acc[8][4];
#pragma unroll
    for (int j = 0; j < 8; ++j)
#pragma unroll
        for (int c = 0; c < 4; ++c) acc[j][c] = 0ull;

    const float* xf = x + (size_t)f * VV * Cin;
    const int nch = Cin >> 3;

    for (int kc = 0; kc < nch; ++kc) {
        __syncthreads();
        // ---- fill activation chunk (4 z-slices incl halo, 8x8 each, 8 ch)
#pragma unroll
        for (int rep = 0; rep < 2; ++rep) {
            int j  = t + rep * 128;      // 0..255
            int lz = j >> 6;             // 0..3  (pz directly)
            int vy = (j >> 3) & 7;
            int vx = j & 7;
            int gz = zbase + lz - 1;
            float val[8];
            if ((unsigned)gz < 8u) {
                const float4* src = (const float4*)(xf + (size_t)(gz * 64 + vy * 8 + vx) * Cin + kc * 8);
                float4 r0 = src[0], r1 = src[1];
                val[0] = r0.x; val[1] = r0.y; val[2] = r0.z; val[3] = r0.w;
                val[4] = r1.x; val[5] = r1.y; val[6] = r1.z; val[7] = r1.w;
            } else {
#pragma unroll
                for (int kk = 0; kk < 8; ++kk) val[kk] = 0.f;
            }
            int p = lz * 100 + (vy + 1) * 10 + (vx + 1);
#pragma unroll
            for (int kk = 0; kk < 8; ++kk) xs[kk * 400 + p] = val[kk];
        }
        // ---- fill weight chunk: 27*8*64 floats = 3456 float4
        {
            float4* wd = (float4*)ws;
            for (int i = t; i < 3456; i += 128) {
                int o  = i >> 7;         // /128 (128 float4 per tap)
                int r  = i & 127;
                int kk = r >> 4;         // /16  (16 float4 per cin)
                int c4 = r & 15;
                wd[i] = *(const float4*)&w[((size_t)o * Cin + (kc * 8 + kk)) * Cout + co0 + c4 * 4];
            }
        }
        __syncthreads();

        const float4* ws4 = (const float4*)ws;
#pragma unroll 1
        for (int kk = 0; kk < 8; ++kk) {
            const float*  xkk = xs + kk * 400 + zl * 100 + gy * 10;
            const float4* wk4 = ws4 + kk * 16 + cg * 2;
#pragma unroll 1
            for (int dz = 0; dz < 3; ++dz) {
#pragma unroll 1
                for (int dy = 0; dy < 3; ++dy) {
                    const float* rp = xkk + dz * 100 + dy * 10;
                    unsigned long long rd[10];
#pragma unroll
                    for (int i = 0; i < 10; ++i) rd[i] = dup_f32x2(rp[i]);
                    const float4* wo4 = wk4 + (size_t)(dz * 9 + dy * 3) * 128;
#pragma unroll
                    for (int dx = 0; dx < 3; ++dx) {
                        F4U2 b0, b1;
                        b0.f = wo4[(size_t)dx * 128];
                        b1.f = wo4[(size_t)dx * 128 + 1];
                        unsigned long long bp0 = b0.u[0], bp1 = b0.u[1];
                        unsigned long long bp2 = b1.u[0], bp3 = b1.u[1];
#pragma unroll
                        for (int j = 0; j < 8; ++j) {
                            unsigned long long a2 = rd[j + dx];
                            fma_f32x2(acc[j][0], a2, bp0);
                            fma_f32x2(acc[j][1], a2, bp1);
                            fma_f32x2(acc[j][2], a2, bp2);
                            fma_f32x2(acc[j][3], a2, bp3);
                        }
                    }
                }
            }
        }
    }

    // ---- epilogue: bias (+residual) (+gelu)
    int co = co0 + cg * 8;
    float bv[8];
#pragma unroll
    for (int c = 0; c < 8; ++c) bv[c] = bias[co + c];
#pragma unroll
    for (int j = 0; j < 8; ++j) {
        int vox = (zbase + zl) * 64 + gy * 8 + j;
        size_t oi = ((size_t)f * VV + vox) * Cout + co;
        float r[8];
#pragma unroll
        for (int c = 0; c < 4; ++c) {
            float lo, hi;
            unpack_f32x2(acc[j][c], lo, hi);
            r[2 * c]     = lo + bv[2 * c];
            r[2 * c + 1] = hi + bv[2 * c + 1];
        }
        if (residual) {
            const float4* rp = (const float4*)(residual + oi);
            float4 r0 = rp[0], r1 = rp[1];
            r[0] += r0.x; r[1] += r0.y; r[2] += r0.z; r[3] += r0.w;
            r[4] += r1.x; r[5] += r1.y; r[6] += r1.z; r[7] += r1.w;
        }
        if (do_gelu) {
#pragma unroll
            for (int c = 0; c < 8; ++c)
                r[c] = 0.5f * r[c] * (1.f + erff(r[c] * 0.7071067811865475f));
        }
        float4* op = (float4*)(y + oi);
        op[0] = make_float4(r[0], r[1], r[2], r[3]);
        op[1] = make_float4(r[4], r[5], r[6], r[7]);
    }
}

// ---------------------------------------------------------------------------
// Attention over time (20 steps) per (b, voxel, head). One warp per unit.
// ---------------------------------------------------------------------------
__global__ void __launch_bounds__(128)
attn_kernel(const float* __restrict__ q, const float* __restrict__ k,
            const float* __restrict__ v, float* __restrict__ o)
{
    __shared__ float sm[4][2380];   // per warp: q 20x33, k 20x33, v 20x33, at 20x20
    int wlocal = threadIdx.x >> 5;
    int lane   = threadIdx.x & 31;
    int wid    = blockIdx.x * 4 + wlocal;     // 0..16383 (B*V*NH)
    int h  = wid & 7;
    int vx = (wid >> 3) & 511;
    int b  = wid >> 12;

    float* qs = sm[wlocal];
    float* ks = qs + 660;
    float* vs = ks + 660;
    float* at = vs + 660;

    size_t base = (size_t)vx * EE + h * HEADD + lane;
#pragma unroll
    for (int s = 0; s < SS; ++s) {
        size_t gi = (size_t)(b * SS + s) * (VV * EE) + base;
        qs[s * 33 + lane] = q[gi];
        ks[s * 33 + lane] = k[gi];
        vs[s * 33 + lane] = v[gi];
    }
    __syncwarp();

    const float scale = 0.17677669529663687f;  // 1/sqrt(32)
    int tt = lane;
#pragma unroll 1
    for (int s = 0; s < SS; ++s) {
        float sc = -1e30f;
        if (tt < SS) {
            float a = 0.f;
#pragma unroll
            for (int d = 0; d < HEADD; ++d)
                a = fmaf(qs[s * 33 + d], ks[tt * 33 + d], a);
            sc = a * scale;
        }
        float m = sc;
#pragma unroll
        for (int off = 16; off > 0; off >>= 1)
            m = fmaxf(m, __shfl_xor_sync(0xffffffffu, m, off));
        float e = (tt < SS) ? expf(sc - m) : 0.f;
        float su = e;
#pragma unroll
        for (int off = 16; off > 0; off >>= 1)
            su += __shfl_xor_sync(0xffffffffu, su, off);
        if (tt < SS) at[s * SS + tt] = e / su;
    }
    __syncwarp();

#pragma unroll 1
    for (int s = 0; s < SS; ++s) {
        float a = 0.f;
#pragma unroll
        for (int t2 = 0; t2 < SS; ++t2)
            a = fmaf(at[s * SS + t2], vs[t2 * 33 + lane], a);
        o[(size_t)(b * SS + s) * (VV * EE) + base] = a;
    }
}

// ---------------------------------------------------------------------------
// Final linear: [40960 x 256] @ [256 x 512] + bias -> logits
// ---------------------------------------------------------------------------
__global__ void __launch_bounds__(256)
linear_kernel(const float* __restrict__ A, const float* __restrict__ Bw,
              const float* __restrict__ bias, float* __restrict__ C)
{
    __shared__ float As[32 * 65];
    __shared__ float Bs[32 * 64];
    int t  = threadIdx.x;
    int tx = t & 15, ty = t >> 4;
    int m0 = blockIdx.x * 64, n0 = blockIdx.y * 64;
    float acc[4][4];
#pragma unroll
    for (int i = 0; i < 4; ++i)
#pragma unroll
        for (int j = 0; j < 4; ++j) acc[i][j] = 0.f;

    for (int kt = 0; kt < 8; ++kt) {
        for (int i = t; i < 2048; i += 256) {
            int r = i >> 5, kk = i & 31;
            As[kk * 65 + r] = A[(size_t)(m0 + r) * EE + kt * 32 + kk];
        }
        for (int i = t; i < 2048; i += 256) {
            int kk = i >> 6, c = i & 63;
            Bs[kk * 64 + c] = Bw[(size_t)(kt * 32 + kk) * NEE + n0 + c];
        }
        __syncthreads();
#pragma unroll
        for (int kk = 0; kk < 32; ++kk) {
            float a[4];
#pragma unroll
            for (int i = 0; i < 4; ++i) a[i] = As[kk * 65 + ty * 4 + i];
            float4 bvv = *(const float4*)&Bs[kk * 64 + tx * 4];
            float bvals[4] = {bvv.x, bvv.y, bvv.z, bvv.w};
#pragma unroll
            for (int i = 0; i < 4; ++i)
#pragma unroll
                for (int j = 0; j < 4; ++j)
                    acc[i][j] = fmaf(a[i], bvals[j], acc[i][j]);
        }
        __syncthreads();
    }
#pragma unroll
    for (int i = 0; i < 4; ++i)
#pragma unroll
        for (int j = 0; j < 4; ++j)
            C[(size_t)(m0 + ty * 4 + i) * NEE + n0 + tx * 4 + j] =
                acc[i][j] + bias[n0 + tx * 4 + j];
}

// ---------------------------------------------------------------------------
// Score transpose: score[b][c][p][v] = logits[b*20+16+p][v][c]
// ---------------------------------------------------------------------------
__global__ void score_kernel(const float* __restrict__ logits, float* __restrict__ out,
                             int out_size)
{
    __shared__ float tile[32][33];
    int bp = blockIdx.z;
    int b = bp >> 2, p = bp & 3;
    int v0 = blockIdx.x * 32, c0 = blockIdx.y * 32;
    int f = b * SS + BPTT + p;
    int t = threadIdx.x;
    int ci = t & 31, vi = t >> 5;     // vi 0..7
#pragma unroll
    for (int r = 0; r < 32; r += 8)
        tile[vi + r][ci] = logits[((size_t)f * VV + v0 + vi + r) * NEE + c0 + ci];
    __syncthreads();
    int vv2 = t & 31, cc = t >> 5;
#pragma unroll
    for (int r = 0; r < 32; r += 8) {
        size_t oidx = (((size_t)(b * NEE + c0 + cc + r)) * PRED + p) * VV + v0 + vv2;
        if (oidx < (size_t)out_size) out[oidx] = tile[vv2][cc + r];
    }
}

// ---------------------------------------------------------------------------
// Per-row log-softmax target loss + argmax. Warp per (b,p,v) row.
// ---------------------------------------------------------------------------
__global__ void loss_argmax_kernel(const float* __restrict__ logits,
                                   const int* __restrict__ ncode,
                                   float* __restrict__ rowloss,
                                   float* __restrict__ out, int write_code)
{
    int wid  = (int)((blockIdx.x * blockDim.x + threadIdx.x) >> 5);
    int lane = threadIdx.x & 31;
    if (wid >= NROWS) return;
    int v = wid & 511, p = (wid >> 9) & 3, b = wid >> 11;
    const float* lp = logits + ((size_t)(b * SS + BPTT + p) * VV + v) * NEE;

    float vals[16];
    float mx = -1e30f;
    int mi = 0;
#pragma unroll
    for (int i = 0; i < 16; ++i) {
        int c = lane + i * 32;
        float xv = lp[c];
        vals[i] = xv;
        if (xv > mx) { mx = xv; mi = c; }
    }
#pragma unroll
    for (int off = 16; off > 0; off >>= 1) {
        float om = __shfl_xor_sync(0xffffffffu, mx, off);
        int   oi = __shfl_xor_sync(0xffffffffu, mi, off);
        if (om > mx || (om == mx && oi < mi)) { mx = om; mi = oi; }
    }
    float se = 0.f;
#pragma unroll
    for (int i = 0; i < 16; ++i) se += expf(vals[i] - mx);
#pragma unroll
    for (int off = 16; off > 0; off >>= 1)
        se += __shfl_xor_sync(0xffffffffu, se, off);

    int tgt = ncode[wid];
    if (lane == (tgt & 31))
        rowloss[wid] = -(vals[tgt >> 5] - mx - logf(se));
    if (write_code && lane == 0)
        out[(size_t)SCORE_SIZE + 1 + wid] = (float)mi;
}

__global__ void loss_reduce_kernel(const float* __restrict__ rowloss,
                                   float* __restrict__ out, int loss_off)
{
    __shared__ float smr[256];
    int t = threadIdx.x;
    float a = 0.f;
    for (int i = t; i < NROWS; i += 256) a += rowloss[i];
    smr[t] = a;
    __syncthreads();
    for (int s = 128; s > 0; s >>= 1) {
        if (t < s) smr[t] += smr[t + s];
        __syncthreads();
    }
    if (t == 0) out[loss_off] = smr[0] * (1.f / (float)NROWS);
}

// ---------------------------------------------------------------------------
// Orchestration
// ---------------------------------------------------------------------------
extern "C" void kernel_launch(void* const* d_in, const int* in_sizes, int n_in,
                              void* d_out, int out_size)
{
    (void)in_sizes; (void)n_in;
    const int*   code   = (const int*)  d_in[0];
    const int*   ncode  = (const int*)  d_in[1];
    const float* emb    = (const float*)d_in[2];
    const float* pos    = (const float*)d_in[3];
    const float* ln1s   = (const float*)d_in[4];
    const float* ln1b   = (const float*)d_in[5];
    const float* ln2s   = (const float*)d_in[6];
    const float* ln2b   = (const float*)d_in[7];
    const float* wq     = (const float*)d_in[8];
    const float* bq     = (const float*)d_in[9];
    const float* wk     = (const float*)d_in[10];
    const float* bk     = (const float*)d_in[11];
    const float* wv     = (const float*)d_in[12];
    const float* bv     = (const float*)d_in[13];
    const float* wo     = (const float*)d_in[14];
    const float* bo     = (const float*)d_in[15];
    const float* w1     = (const float*)d_in[16];
    const float* b1     = (const float*)d_in[17];
    const float* w2     = (const float*)d_in[18];
    const float* b2     = (const float*)d_in[19];
    const float* lnfs   = (const float*)d_in[20];
    const float* lnfb   = (const float*)d_in[21];
    const float* decw   = (const float*)d_in[22];
    const float* decb   = (const float*)d_in[23];
    const float* declns = (const float*)d_in[24];
    const float* declnb = (const float*)d_in[25];
    const float* linw   = (const float*)d_in[26];
    const float* linb   = (const float*)d_in[27];
    float* out = (float*)d_out;

    float *px, *ph, *pq, *pk, *pv, *pa, *phid, *plog, *prl;
    cudaGetSymbolAddress((void**)&px,   g_x);
    cudaGetSymbolAddress((void**)&ph,   g_h);
    cudaGetSymbolAddress((void**)&pq,   g_q);
    cudaGetSymbolAddress((void**)&pk,   g_k);
    cudaGetSymbolAddress((void**)&pv,   g_v);
    cudaGetSymbolAddress((void**)&pa,   g_ao);
    cudaGetSymbolAddress((void**)&phid, g_hid);
    cudaGetSymbolAddress((void**)&plog, g_logits);
    cudaGetSymbolAddress((void**)&prl,  g_rowloss);

    cudaFuncSetAttribute(conv3d_kernel,
                         cudaFuncAttributeMaxDynamicSharedMemorySize,
                         CONV_SMEM_BYTES);

    const int ROWS = FF * VV;                  // 40960
    const int LN_BLOCKS = (ROWS * 32) / 256;   // 5120
    const size_t WEE = 27 * 256 * 256;         // per-layer E->E weight stride
    const size_t WEH = 27 * 256 * 512;         // per-layer E->HID (== HID->E)

    embed_kernel<<<(int)((FVE + 255) / 256), 256>>>(code, emb, pos, px);

    dim3 cgE(FF, 4, 4);   // Cout=256
    dim3 cgH(FF, 8, 4);   // Cout=512
    for (int i = 0; i < 4; ++i) {
        ln_kernel<<<LN_BLOCKS, 256>>>(px, ph, ln1s + i * EE, ln1b + i * EE, ROWS);
        conv3d_kernel<<<cgE, 128, CONV_SMEM_BYTES>>>(ph, wq + i * WEE, bq + i * EE, nullptr, pq, 256, 256, 0);
        conv3d_kernel<<<cgE, 128, CONV_SMEM_BYTES>>>(ph, wk + i * WEE, bk + i * EE, nullptr, pk, 256, 256, 0);
        conv3d_kernel<<<cgE, 128, CONV_SMEM_BYTES>>>(ph, wv + i * WEE, bv + i * EE, nullptr, pv, 256, 256, 0);
        attn_kernel<<<4096, 128>>>(pq, pk, pv, pa);
        conv3d_kernel<<<cgE, 128, CONV_SMEM_BYTES>>>(pa, wo + i * WEE, bo + i * EE, px, px, 256, 256, 0);
        ln_kernel<<<LN_BLOCKS, 256>>>(px, ph, ln2s + i * EE, ln2b + i * EE, ROWS);
        conv3d_kernel<<<cgH, 128, CONV_SMEM_BYTES>>>(ph, w1 + i * WEH, b1 + i * HIDD, nullptr, phid, 256, 512, 1);
        conv3d_kernel<<<cgE, 128, CONV_SMEM_BYTES>>>(phid, w2 + i * WEH, b2 + i * EE, px, px, 512, 256, 0);
    }

    ln_kernel<<<LN_BLOCKS, 256>>>(px, ph, lnfs, lnfb, ROWS);
    conv3d_kernel<<<cgE, 128, CONV_SMEM_BYTES>>>(ph, decw, decb, nullptr, pq, 256, 256, 1);
    ln_kernel<<<LN_BLOCKS, 256>>>(pq, pk, declns, declnb, ROWS);
    linear_kernel<<<dim3(ROWS / 64, NEE / 64), 256>>>(pk, linw, linb, plog);

    if (out_size >= SCORE_SIZE) {
        dim3 sg(16, 16, 16);
        score_kernel<<<sg, 256>>>(plog, out, out_size);
    }
    int write_code = (out_size >= SCORE_SIZE + 1 + NROWS) ? 1 : 0;
    loss_argmax_kernel<<<(NROWS * 32) / 256, 256>>>(plog, ncode, prl, out, write_code);

    int loss_off = -1;
    if (out_size == 1) loss_off = 0;
    else if (out_size > SCORE_SIZE) loss_off = SCORE_SIZE;
    if (loss_off >= 0)
        loss_reduce_kernel<<<1, 256>>>(prl, out, loss_off);
}

// round 6
// speedup vs baseline: 1.1891x; 1.0350x over previous
#include <cuda_runtime.h>
#include <cuda_bf16.h>
#include <math.h>

// ---------------------------------------------------------------------------
// Problem constants
// ---------------------------------------------------------------------------
#define BB    4          // batch
#define BPTT  16
#define PRED  4
#define SS    20         // S = BPTT + PRED
#define VV    512        // 8*8*8 voxels
#define EE    256
#define NHH   8
#define HEADD 32
#define HIDD  512
#define NEE   512
#define FF    80         // B * S frames

#define FVE   ((size_t)FF * VV * EE)    // 10,485,760
#define FVH   ((size_t)FF * VV * HIDD)  // 20,971,520
#define SCORE_SIZE (BB * NEE * PRED * VV)  // 4,194,304
#define NROWS (BB * PRED * VV)             // 8192

// ---------------------------------------------------------------------------
// Scratch (allocation-free: __device__ globals)
// ---------------------------------------------------------------------------
__device__ float g_x[FVE];
__device__ float g_h[FVE];
__device__ float g_q[FVE];
__device__ float g_k[FVE];
__device__ float g_v[FVE];
__device__ float g_ao[FVE];
__device__ float g_hid[FVH];
__device__ float g_logits[FVH];
__device__ float g_rowloss[NROWS];

// ---------------------------------------------------------------------------
// Packed fp32x2 helpers (sm_100+). Numerically identical to 2x scalar FFMA.
// ---------------------------------------------------------------------------
__device__ __forceinline__ unsigned long long dup_f32x2(float x) {
    unsigned long long r;
    asm("mov.b64 %0, {%1, %1};" : "=l"(r) : "f"(x));
    return r;
}
__device__ __forceinline__ void fma_f32x2(unsigned long long& acc,
                                          unsigned long long a,
                                          unsigned long long b) {
    asm("fma.rn.f32x2 %0, %1, %2, %0;" : "+l"(acc) : "l"(a), "l"(b));
}
__device__ __forceinline__ void unpack_f32x2(unsigned long long p, float& lo, float& hi) {
    asm("mov.b64 {%0, %1}, %2;" : "=f"(lo), "=f"(hi) : "l"(p));
}
union F4U2 { float4 f; unsigned long long u[2]; };

// ---------------------------------------------------------------------------
// Embedding: x[b,s,v,e] = emb[tok][e] + pos[s][e]
// ---------------------------------------------------------------------------
__global__ void embed_kernel(const int* __restrict__ code,
                             const float* __restrict__ emb,
                             const float* __restrict__ pos,
                             float* __restrict__ x)
{
    size_t idx = (size_t)blockIdx.x * blockDim.x + threadIdx.x;
    if (idx >= FVE) return;
    int e = (int)(idx & 255);
    int v = (int)((idx >> 8) & 511);
    int f = (int)(idx >> 17);            // /(256*512)
    int b = f / SS, s = f % SS;
    int tok = (s < BPTT) ? code[((b * BPTT + s) << 9) + v] : NEE;
    x[idx] = emb[tok * EE + e] + pos[s * EE + e];
}

// ---------------------------------------------------------------------------
// LayerNorm over last dim (E=256), warp per row
// ---------------------------------------------------------------------------
__global__ void ln_kernel(const float* __restrict__ in, float* __restrict__ out,
                          const float* __restrict__ sc, const float* __restrict__ bi,
                          int rows)
{
    int wid  = (int)((blockIdx.x * blockDim.x + threadIdx.x) >> 5);
    int lane = threadIdx.x & 31;
    if (wid >= rows) return;
    const float* p = in + (size_t)wid * EE;
    float v8[8];
    float s = 0.f, sq = 0.f;
#pragma unroll
    for (int i = 0; i < 8; ++i) {
        float xv = p[lane + i * 32];
        v8[i] = xv;
        s += xv;
        sq = fmaf(xv, xv, sq);
    }
#pragma unroll
    for (int off = 16; off > 0; off >>= 1) {
        s  += __shfl_xor_sync(0xffffffffu, s, off);
        sq += __shfl_xor_sync(0xffffffffu, sq, off);
    }
    float m   = s * (1.f / 256.f);
    float var = sq * (1.f / 256.f) - m * m;
    if (var < 0.f) var = 0.f;
    float inv = rsqrtf(var + 1e-5f);
    float* q = out + (size_t)wid * EE;
#pragma unroll
    for (int i = 0; i < 8; ++i) {
        int e = lane + i * 32;
        q[e] = (v8[i] - m) * inv * sc[e] + bi[e];
    }
}

// ---------------------------------------------------------------------------
// 3D conv, 3x3x3, SAME padding, implicit GEMM.
//   x: [F][512][Cin]   w: [27][Cin][Cout]   y: [F][512][Cout]
// Block: one frame f, one 64-wide cout tile, one 2-slice z quarter.
// SMEM: padded activation chunk xs[8ch][4z * 10y * 10x] + weight chunk
// ws[27][8ch][64co].
// Lane map: warp = 4 cout-octets x 8 rows (halves distinct weight bytes per
// warp per tap vs 8x4). Activation rows loaded via LDS.64 (8B-aligned).
// FMAs are packed fma.rn.f32x2 over cout pairs.
// ---------------------------------------------------------------------------
#define CONV_SMEM_FLOATS (8 * 400 + 27 * 8 * 64)   // 3200 + 13824 = 17024
#define CONV_SMEM_BYTES  (CONV_SMEM_FLOATS * 4)    // 68096

__global__ void __launch_bounds__(128)
conv3d_kernel(const float* __restrict__ x, const float* __restrict__ w,
              const float* __restrict__ bias, const float* __restrict__ residual,
              float* __restrict__ y, int Cin, int Cout, int do_gelu)
{
    extern __shared__ float smem[];
    float* xs = smem;            // [8][400]
    float* ws = smem + 3200;     // [27][8][64]

    const int t     = threadIdx.x;
    const int f     = blockIdx.x;
    const int co0   = blockIdx.y * 64;
    const int zbase = blockIdx.z * 2;

    // lane map: warp covers 4 cout-octets x 8 rows
    //   bits: b0-b1 = cg_lo, b2-b4 = row_lo, b5 = cg_hi, b6 = row_hi
    const int cg  = (t & 3) | (((t >> 5) & 1) << 2);   // 0..7 cout octet
    const int row = ((t >> 2) & 7) | (((t >> 6) & 1) << 3);  // 0..15
    const int zl = row >> 3;     // 0..1
    const int gy = row & 7;      // 0..7

    for (int i = t; i < 3200; i += 128) xs[i] = 0.f;

    unsigned long long acc[8][4];
#pragma unroll
    for (int j = 0; j < 8; ++j)
#pragma unroll
        for (int c = 0; c < 4; ++c) acc[j][c] = 0ull;

    const float* xf = x + (size_t)f * VV * Cin;
    const int nch = Cin >> 3;

    for (int kc = 0; kc < nch; ++kc) {
        __syncthreads();
        // ---- fill activation chunk (4 z-slices incl halo, 8x8 each, 8 ch)
#pragma unroll
        for (int rep = 0; rep < 2; ++rep) {
            int j  = t + rep * 128;      // 0..255
            int lz = j >> 6;             // 0..3  (pz directly)
            int vy = (j >> 3) & 7;
            int vx = j & 7;
            int gz = zbase + lz - 1;
            float val[8];
            if ((unsigned)gz < 8u) {
                const float4* src = (const float4*)(xf + (size_t)(gz * 64 + vy * 8 + vx) * Cin + kc * 8);
                float4 r0 = src[0], r1 = src[1];
                val[0] = r0.x; val[1] = r0.y; val[2] = r0.z; val[3] = r0.w;
                val[4] = r1.x; val[5] = r1.y; val[6] = r1.z; val[7] = r1.w;
            } else {
#pragma unroll
                for (int kk = 0; kk < 8; ++kk) val[kk] = 0.f;
            }
            int p = lz * 100 + (vy + 1) * 10 + (vx + 1);
#pragma unroll
            for (int kk = 0; kk < 8; ++kk) xs[kk * 400 + p] = val[kk];
        }
        // ---- fill weight chunk: 27*8*64 floats = 3456 float4
        {
            float4* wd = (float4*)ws;
            for (int i = t; i < 3456; i += 128) {
                int o  = i >> 7;         // /128 (128 float4 per tap)
                int r  = i & 127;
                int kk = r >> 4;         // /16  (16 float4 per cin)
                int c4 = r & 15;
                wd[i] = *(const float4*)&w[((size_t)o * Cin + (kc * 8 + kk)) * Cout + co0 + c4 * 4];
            }
        }
        __syncthreads();

        const float4* ws4 = (const float4*)ws;
#pragma unroll 1
        for (int kk = 0; kk < 8; ++kk) {
            const float*  xkk = xs + kk * 400;
            const float4* wk4 = ws4 + kk * 16 + cg * 2;
#pragma unroll 1
            for (int dz = 0; dz < 3; ++dz) {
#pragma unroll 1
                for (int dy = 0; dy < 3; ++dy) {
                    // 10-float halo row, 8B-aligned -> 5x LDS.64
                    const float2* rp2 = (const float2*)(xkk + (zl + dz) * 100 + (gy + dy) * 10);
                    float2 p0 = rp2[0], p1 = rp2[1], p2 = rp2[2], p3 = rp2[3], p4 = rp2[4];
                    unsigned long long rd[10];
                    rd[0] = dup_f32x2(p0.x); rd[1] = dup_f32x2(p0.y);
                    rd[2] = dup_f32x2(p1.x); rd[3] = dup_f32x2(p1.y);
                    rd[4] = dup_f32x2(p2.x); rd[5] = dup_f32x2(p2.y);
                    rd[6] = dup_f32x2(p3.x); rd[7] = dup_f32x2(p3.y);
                    rd[8] = dup_f32x2(p4.x); rd[9] = dup_f32x2(p4.y);
                    const float4* wo4 = wk4 + (size_t)(dz * 9 + dy * 3) * 128;
#pragma unroll
                    for (int dx = 0; dx < 3; ++dx) {
                        F4U2 b0, b1;
                        b0.f = wo4[(size_t)dx * 128];
                        b1.f = wo4[(size_t)dx * 128 + 1];
                        unsigned long long bp0 = b0.u[0], bp1 = b0.u[1];
                        unsigned long long bp2 = b1.u[0], bp3 = b1.u[1];
#pragma unroll
                        for (int j = 0; j < 8; ++j) {
                            unsigned long long a2 = rd[j + dx];
                            fma_f32x2(acc[j][0], a2, bp0);
                            fma_f32x2(acc[j][1], a2, bp1);
                            fma_f32x2(acc[j][2], a2, bp2);
                            fma_f32x2(acc[j][3], a2, bp3);
                        }
                    }
                }
            }
        }
    }

    // ---- epilogue: bias (+residual) (+gelu)
    int co = co0 + cg * 8;
    float bv[8];
#pragma unroll
    for (int c = 0; c < 8; ++c) bv[c] = bias[co + c];
#pragma unroll
    for (int j = 0; j < 8; ++j) {
        int vox = (zbase + zl) * 64 + gy * 8 + j;
        size_t oi = ((size_t)f * VV + vox) * Cout + co;
        float r[8];
#pragma unroll
        for (int c = 0; c < 4; ++c) {
            float lo, hi;
            unpack_f32x2(acc[j][c], lo, hi);
            r[2 * c]     = lo + bv[2 * c];
            r[2 * c + 1] = hi + bv[2 * c + 1];
        }
        if (residual) {
            const float4* rp = (const float4*)(residual + oi);
            float4 r0 = rp[0], r1 = rp[1];
            r[0] += r0.x; r[1] += r0.y; r[2] += r0.z; r[3] += r0.w;
            r[4] += r1.x; r[5] += r1.y; r[6] += r1.z; r[7] += r1.w;
        }
        if (do_gelu) {
#pragma unroll
            for (int c = 0; c < 8; ++c)
                r[c] = 0.5f * r[c] * (1.f + erff(r[c] * 0.7071067811865475f));
        }
        float4* op = (float4*)(y + oi);
        op[0] = make_float4(r[0], r[1], r[2], r[3]);
        op[1] = make_float4(r[4], r[5], r[6], r[7]);
    }
}

// ---------------------------------------------------------------------------
// Attention over time (20 steps) per (b, voxel, head). One warp per unit.
// ---------------------------------------------------------------------------
__global__ void __launch_bounds__(128)
attn_kernel(const float* __restrict__ q, const float* __restrict__ k,
            const float* __restrict__ v, float* __restrict__ o)
{
    __shared__ float sm[4][2380];   // per warp: q 20x33, k 20x33, v 20x33, at 20x20
    int wlocal = threadIdx.x >> 5;
    int lane   = threadIdx.x & 31;
    int wid    = blockIdx.x * 4 + wlocal;     // 0..16383 (B*V*NH)
    int h  = wid & 7;
    int vx = (wid >> 3) & 511;
    int b  = wid >> 12;

    float* qs = sm[wlocal];
    float* ks = qs + 660;
    float* vs = ks + 660;
    float* at = vs + 660;

    size_t base = (size_t)vx * EE + h * HEADD + lane;
#pragma unroll
    for (int s = 0; s < SS; ++s) {
        size_t gi = (size_t)(b * SS + s) * (VV * EE) + base;
        qs[s * 33 + lane] = q[gi];
        ks[s * 33 + lane] = k[gi];
        vs[s * 33 + lane] = v[gi];
    }
    __syncwarp();

    const float scale = 0.17677669529663687f;  // 1/sqrt(32)
    int tt = lane;
#pragma unroll 1
    for (int s = 0; s < SS; ++s) {
        float sc = -1e30f;
        if (tt < SS) {
            float a = 0.f;
#pragma unroll
            for (int d = 0; d < HEADD; ++d)
                a = fmaf(qs[s * 33 + d], ks[tt * 33 + d], a);
            sc = a * scale;
        }
        float m = sc;
#pragma unroll
        for (int off = 16; off > 0; off >>= 1)
            m = fmaxf(m, __shfl_xor_sync(0xffffffffu, m, off));
        float e = (tt < SS) ? expf(sc - m) : 0.f;
        float su = e;
#pragma unroll
        for (int off = 16; off > 0; off >>= 1)
            su += __shfl_xor_sync(0xffffffffu, su, off);
        if (tt < SS) at[s * SS + tt] = e / su;
    }
    __syncwarp();

#pragma unroll 1
    for (int s = 0; s < SS; ++s) {
        float a = 0.f;
#pragma unroll
        for (int t2 = 0; t2 < SS; ++t2)
            a = fmaf(at[s * SS + t2], vs[t2 * 33 + lane], a);
        o[(size_t)(b * SS + s) * (VV * EE) + base] = a;
    }
}

// ---------------------------------------------------------------------------
// Final linear: [40960 x 256] @ [256 x 512] + bias -> logits
// ---------------------------------------------------------------------------
__global__ void __launch_bounds__(256)
linear_kernel(const float* __restrict__ A, const float* __restrict__ Bw,
              const float* __restrict__ bias, float* __restrict__ C)
{
    __shared__ float As[32 * 65];
    __shared__ float Bs[32 * 64];
    int t  = threadIdx.x;
    int tx = t & 15, ty = t >> 4;
    int m0 = blockIdx.x * 64, n0 = blockIdx.y * 64;
    float acc[4][4];
#pragma unroll
    for (int i = 0; i < 4; ++i)
#pragma unroll
        for (int j = 0; j < 4; ++j) acc[i][j] = 0.f;

    for (int kt = 0; kt < 8; ++kt) {
        for (int i = t; i < 2048; i += 256) {
            int r = i >> 5, kk = i & 31;
            As[kk * 65 + r] = A[(size_t)(m0 + r) * EE + kt * 32 + kk];
        }
        for (int i = t; i < 2048; i += 256) {
            int kk = i >> 6, c = i & 63;
            Bs[kk * 64 + c] = Bw[(size_t)(kt * 32 + kk) * NEE + n0 + c];
        }
        __syncthreads();
#pragma unroll
        for (int kk = 0; kk < 32; ++kk) {
            float a[4];
#pragma unroll
            for (int i = 0; i < 4; ++i) a[i] = As[kk * 65 + ty * 4 + i];
            float4 bvv = *(const float4*)&Bs[kk * 64 + tx * 4];
            float bvals[4] = {bvv.x, bvv.y, bvv.z, bvv.w};
#pragma unroll
            for (int i = 0; i < 4; ++i)
#pragma unroll
                for (int j = 0; j < 4; ++j)
                    acc[i][j] = fmaf(a[i], bvals[j], acc[i][j]);
        }
        __syncthreads();
    }
#pragma unroll
    for (int i = 0; i < 4; ++i)
#pragma unroll
        for (int j = 0; j < 4; ++j)
            C[(size_t)(m0 + ty * 4 + i) * NEE + n0 + tx * 4 + j] =
                acc[i][j] + bias[n0 + tx * 4 + j];
}

// ---------------------------------------------------------------------------
// Score transpose: score[b][c][p][v] = logits[b*20+16+p][v][c]
// ---------------------------------------------------------------------------
__global__ void score_kernel(const float* __restrict__ logits, float* __restrict__ out,
                             int out_size)
{
    __shared__ float tile[32][33];
    int bp = blockIdx.z;
    int b = bp >> 2, p = bp & 3;
    int v0 = blockIdx.x * 32, c0 = blockIdx.y * 32;
    int f = b * SS + BPTT + p;
    int t = threadIdx.x;
    int ci = t & 31, vi = t >> 5;     // vi 0..7
#pragma unroll
    for (int r = 0; r < 32; r += 8)
        tile[vi + r][ci] = logits[((size_t)f * VV + v0 + vi + r) * NEE + c0 + ci];
    __syncthreads();
    int vv2 = t & 31, cc = t >> 5;
#pragma unroll
    for (int r = 0; r < 32; r += 8) {
        size_t oidx = (((size_t)(b * NEE + c0 + cc + r)) * PRED + p) * VV + v0 + vv2;
        if (oidx < (size_t)out_size) out[oidx] = tile[vv2][cc + r];
    }
}

// ---------------------------------------------------------------------------
// Per-row log-softmax target loss + argmax. Warp per (b,p,v) row.
// ---------------------------------------------------------------------------
__global__ void loss_argmax_kernel(const float* __restrict__ logits,
                                   const int* __restrict__ ncode,
                                   float* __restrict__ rowloss,
                                   float* __restrict__ out, int write_code)
{
    int wid  = (int)((blockIdx.x * blockDim.x + threadIdx.x) >> 5);
    int lane = threadIdx.x & 31;
    if (wid >= NROWS) return;
    int v = wid & 511, p = (wid >> 9) & 3, b = wid >> 11;
    const float* lp = logits + ((size_t)(b * SS + BPTT + p) * VV + v) * NEE;

    float vals[16];
    float mx = -1e30f;
    int mi = 0;
#pragma unroll
    for (int i = 0; i < 16; ++i) {
        int c = lane + i * 32;
        float xv = lp[c];
        vals[i] = xv;
        if (xv > mx) { mx = xv; mi = c; }
    }
#pragma unroll
    for (int off = 16; off > 0; off >>= 1) {
        float om = __shfl_xor_sync(0xffffffffu, mx, off);
        int   oi = __shfl_xor_sync(0xffffffffu, mi, off);
        if (om > mx || (om == mx && oi < mi)) { mx = om; mi = oi; }
    }
    float se = 0.f;
#pragma unroll
    for (int i = 0; i < 16; ++i) se += expf(vals[i] - mx);
#pragma unroll
    for (int off = 16; off > 0; off >>= 1)
        se += __shfl_xor_sync(0xffffffffu, se, off);

    int tgt = ncode[wid];
    if (lane == (tgt & 31))
        rowloss[wid] = -(vals[tgt >> 5] - mx - logf(se));
    if (write_code && lane == 0)
        out[(size_t)SCORE_SIZE + 1 + wid] = (float)mi;
}

__global__ void loss_reduce_kernel(const float* __restrict__ rowloss,
                                   float* __restrict__ out, int loss_off)
{
    __shared__ float smr[256];
    int t = threadIdx.x;
    float a = 0.f;
    for (int i = t; i < NROWS; i += 256) a += rowloss[i];
    smr[t] = a;
    __syncthreads();
    for (int s = 128; s > 0; s >>= 1) {
        if (t < s) smr[t] += smr[t + s];
        __syncthreads();
    }
    if (t == 0) out[loss_off] = smr[0] * (1.f / (float)NROWS);
}

// ---------------------------------------------------------------------------
// Orchestration
// ---------------------------------------------------------------------------
extern "C" void kernel_launch(void* const* d_in, const int* in_sizes, int n_in,
                              void* d_out, int out_size)
{
    (void)in_sizes; (void)n_in;
    const int*   code   = (const int*)  d_in[0];
    const int*   ncode  = (const int*)  d_in[1];
    const float* emb    = (const float*)d_in[2];
    const float* pos    = (const float*)d_in[3];
    const float* ln1s   = (const float*)d_in[4];
    const float* ln1b   = (const float*)d_in[5];
    const float* ln2s   = (const float*)d_in[6];
    const float* ln2b   = (const float*)d_in[7];
    const float* wq     = (const float*)d_in[8];
    const float* bq     = (const float*)d_in[9];
    const float* wk     = (const float*)d_in[10];
    const float* bk     = (const float*)d_in[11];
    const float* wv     = (const float*)d_in[12];
    const float* bv     = (const float*)d_in[13];
    const float* wo     = (const float*)d_in[14];
    const float* bo     = (const float*)d_in[15];
    const float* w1     = (const float*)d_in[16];
    const float* b1     = (const float*)d_in[17];
    const float* w2     = (const float*)d_in[18];
    const float* b2     = (const float*)d_in[19];
    const float* lnfs   = (const float*)d_in[20];
    const float* lnfb   = (const float*)d_in[21];
    const float* decw   = (const float*)d_in[22];
    const float* decb   = (const float*)d_in[23];
    const float* declns = (const float*)d_in[24];
    const float* declnb = (const float*)d_in[25];
    const float* linw   = (const float*)d_in[26];
    const float* linb   = (const float*)d_in[27];
    float* out = (float*)d_out;

    float *px, *ph, *pq, *pk, *pv, *pa, *phid, *plog, *prl;
    cudaGetSymbolAddress((void**)&px,   g_x);
    cudaGetSymbolAddress((void**)&ph,   g_h);
    cudaGetSymbolAddress((void**)&pq,   g_q);
    cudaGetSymbolAddress((void**)&pk,   g_k);
    cudaGetSymbolAddress((void**)&pv,   g_v);
    cudaGetSymbolAddress((void**)&pa,   g_ao);
    cudaGetSymbolAddress((void**)&phid, g_hid);
    cudaGetSymbolAddress((void**)&plog, g_logits);
    cudaGetSymbolAddress((void**)&prl,  g_rowloss);

    cudaFuncSetAttribute(conv3d_kernel,
                         cudaFuncAttributeMaxDynamicSharedMemorySize,
                         CONV_SMEM_BYTES);

    const int ROWS = FF * VV;                  // 40960
    const int LN_BLOCKS = (ROWS * 32) / 256;   // 5120
    const size_t WEE = 27 * 256 * 256;         // per-layer E->E weight stride
    const size_t WEH = 27 * 256 * 512;         // per-layer E->HID (== HID->E)

    embed_kernel<<<(int)((FVE + 255) / 256), 256>>>(code, emb, pos, px);

    dim3 cgE(FF, 4, 4);   // Cout=256
    dim3 cgH(FF, 8, 4);   // Cout=512
    for (int i = 0; i < 4; ++i) {
        ln_kernel<<<LN_BLOCKS, 256>>>(px, ph, ln1s + i * EE, ln1b + i * EE, ROWS);
        conv3d_kernel<<<cgE, 128, CONV_SMEM_BYTES>>>(ph, wq + i * WEE, bq + i * EE, nullptr, pq, 256, 256, 0);
        conv3d_kernel<<<cgE, 128, CONV_SMEM_BYTES>>>(ph, wk + i * WEE, bk + i * EE, nullptr, pk, 256, 256, 0);
        conv3d_kernel<<<cgE, 128, CONV_SMEM_BYTES>>>(ph, wv + i * WEE, bv + i * EE, nullptr, pv, 256, 256, 0);
        attn_kernel<<<4096, 128>>>(pq, pk, pv, pa);
        conv3d_kernel<<<cgE, 128, CONV_SMEM_BYTES>>>(pa, wo + i * WEE, bo + i * EE, px, px, 256, 256, 0);
        ln_kernel<<<LN_BLOCKS, 256>>>(px, ph, ln2s + i * EE, ln2b + i * EE, ROWS);
        conv3d_kernel<<<cgH, 128, CONV_SMEM_BYTES>>>(ph, w1 + i * WEH, b1 + i * HIDD, nullptr, phid, 256, 512, 1);
        conv3d_kernel<<<cgE, 128, CONV_SMEM_BYTES>>>(phid, w2 + i * WEH, b2 + i * EE, px, px, 512, 256, 0);
    }

    ln_kernel<<<LN_BLOCKS, 256>>>(px, ph, lnfs, lnfb, ROWS);
    conv3d_kernel<<<cgE, 128, CONV_SMEM_BYTES>>>(ph, decw, decb, nullptr, pq, 256, 256, 1);
    ln_kernel<<<LN_BLOCKS, 256>>>(pq, pk, declns, declnb, ROWS);
    linear_kernel<<<dim3(ROWS / 64, NEE / 64), 256>>>(pk, linw, linb, plog);

    if (out_size >= SCORE_SIZE) {
        dim3 sg(16, 16, 16);
        score_kernel<<<sg, 256>>>(plog, out, out_size);
    }
    int write_code = (out_size >= SCORE_SIZE + 1 + NROWS) ? 1 : 0;
    loss_argmax_kernel<<<(NROWS * 32) / 256, 256>>>(plog, ncode, prl, out, write_code);

    int loss_off = -1;
    if (out_size == 1) loss_off = 0;
    else if (out_size > SCORE_SIZE) loss_off = SCORE_SIZE;
    if (loss_off >= 0)
        loss_reduce_kernel<<<1, 256>>>(prl, out, loss_off);
}

// round 7
// speedup vs baseline: 1.2368x; 1.0401x over previous
#include <cuda_runtime.h>
#include <cuda_bf16.h>
#include <math.h>

// ---------------------------------------------------------------------------
// Problem constants
// ---------------------------------------------------------------------------
#define BB    4          // batch
#define BPTT  16
#define PRED  4
#define SS    20         // S = BPTT + PRED
#define VV    512        // 8*8*8 voxels
#define EE    256
#define NHH   8
#define HEADD 32
#define HIDD  512
#define NEE   512
#define FF    80         // B * S frames

#define FVE   ((size_t)FF * VV * EE)    // 10,485,760
#define FVH   ((size_t)FF * VV * HIDD)  // 20,971,520
#define SCORE_SIZE (BB * NEE * PRED * VV)  // 4,194,304
#define NROWS (BB * PRED * VV)             // 8192

// ---------------------------------------------------------------------------
// Scratch (allocation-free: __device__ globals)
// ---------------------------------------------------------------------------
__device__ float g_x[FVE];
__device__ float g_h[FVE];
__device__ float g_q[FVE];
__device__ float g_k[FVE];
__device__ float g_v[FVE];
__device__ float g_ao[FVE];
__device__ float g_hid[FVH];
__device__ float g_logits[FVH];
__device__ float g_rowloss[NROWS];

// ---------------------------------------------------------------------------
// Packed fp32x2 helpers (sm_100+). Numerically identical to 2x scalar FFMA.
// ---------------------------------------------------------------------------
__device__ __forceinline__ unsigned long long dup_f32x2(float x) {
    unsigned long long r;
    asm("mov.b64 %0, {%1, %1};" : "=l"(r) : "f"(x));
    return r;
}
__device__ __forceinline__ void fma_f32x2(unsigned long long& acc,
                                          unsigned long long a,
                                          unsigned long long b) {
    asm("fma.rn.f32x2 %0, %1, %2, %0;" : "+l"(acc) : "l"(a), "l"(b));
}
__device__ __forceinline__ void unpack_f32x2(unsigned long long p, float& lo, float& hi) {
    asm("mov.b64 {%0, %1}, %2;" : "=f"(lo), "=f"(hi) : "l"(p));
}
union F4U2 { float4 f; unsigned long long u[2]; };

// ---------------------------------------------------------------------------
// Embedding: x[b,s,v,e] = emb[tok][e] + pos[s][e]
// ---------------------------------------------------------------------------
__global__ void embed_kernel(const int* __restrict__ code,
                             const float* __restrict__ emb,
                             const float* __restrict__ pos,
                             float* __restrict__ x)
{
    size_t idx = (size_t)blockIdx.x * blockDim.x + threadIdx.x;
    if (idx >= FVE) return;
    int e = (int)(idx & 255);
    int v = (int)((idx >> 8) & 511);
    int f = (int)(idx >> 17);            // /(256*512)
    int b = f / SS, s = f % SS;
    int tok = (s < BPTT) ? code[((b * BPTT + s) << 9) + v] : NEE;
    x[idx] = emb[tok * EE + e] + pos[s * EE + e];
}

// ---------------------------------------------------------------------------
// LayerNorm over last dim (E=256), warp per row
// ---------------------------------------------------------------------------
__global__ void ln_kernel(const float* __restrict__ in, float* __restrict__ out,
                          const float* __restrict__ sc, const float* __restrict__ bi,
                          int rows)
{
    int wid  = (int)((blockIdx.x * blockDim.x + threadIdx.x) >> 5);
    int lane = threadIdx.x & 31;
    if (wid >= rows) return;
    const float* p = in + (size_t)wid * EE;
    float v8[8];
    float s = 0.f, sq = 0.f;
#pragma unroll
    for (int i = 0; i < 8; ++i) {
        float xv = p[lane + i * 32];
        v8[i] = xv;
        s += xv;
        sq = fmaf(xv, xv, sq);
    }
#pragma unroll
    for (int off = 16; off > 0; off >>= 1) {
        s  += __shfl_xor_sync(0xffffffffu, s, off);
        sq += __shfl_xor_sync(0xffffffffu, sq, off);
    }
    float m   = s * (1.f / 256.f);
    float var = sq * (1.f / 256.f) - m * m;
    if (var < 0.f) var = 0.f;
    float inv = rsqrtf(var + 1e-5f);
    float* q = out + (size_t)wid * EE;
#pragma unroll
    for (int i = 0; i < 8; ++i) {
        int e = lane + i * 32;
        q[e] = (v8[i] - m) * inv * sc[e] + bi[e];
    }
}

// ---------------------------------------------------------------------------
// 3D conv, 3x3x3, SAME padding, implicit GEMM.
//   x: [F][512][Cin]   w: [27][Cin][Cout]   y: [F][512][Cout]
// Block: one frame f, one 64-wide cout tile, one 2-slice z quarter.
// cin chunk = 4 (34KB smem/CTA -> 4 CTAs/SM, 16 warps: latency hiding).
// SMEM: padded activation chunk xs[4ch][4z * 10y * 10x] + weight chunk
// ws[27][4ch][64co].
// Lane map: warp = 4 cout-octets x 8 rows. Activation rows via LDS.64.
// FMAs are packed fma.rn.f32x2 over cout pairs.
// ---------------------------------------------------------------------------
#define KCH 4
#define CONV_SMEM_FLOATS (KCH * 400 + 27 * KCH * 64)   // 1600 + 6912 = 8512
#define CONV_SMEM_BYTES  (CONV_SMEM_FLOATS * 4)        // 34048

__global__ void __launch_bounds__(128, 4)
conv3d_kernel(const float* __restrict__ x, const float* __restrict__ w,
              const float* __restrict__ bias, const float* __restrict__ residual,
              float* __restrict__ y, int Cin, int Cout, int do_gelu)
{
    extern __shared__ float smem[];
    float* xs = smem;                 // [4][400]
    float* ws = smem + KCH * 400;     // [27][4][64]

    const int t     = threadIdx.x;
    const int f     = blockIdx.x;
    const int co0   = blockIdx.y * 64;
    const int zbase = blockIdx.z * 2;

    // lane map: warp covers 4 cout-octets x 8 rows
    const int cg  = (t & 3) | (((t >> 5) & 1) << 2);          // 0..7 cout octet
    const int row = ((t >> 2) & 7) | (((t >> 6) & 1) << 3);   // 0..15
    const int zl = row >> 3;     // 0..1
    const int gy = row & 7;      // 0..7

    for (int i = t; i < KCH * 400; i += 128) xs[i] = 0.f;

    unsigned long long acc[8][4];
#pragma unroll
    for (int j = 0; j < 8; ++j)
#pragma unroll
        for (int c = 0; c < 4; ++c) acc[j][c] = 0ull;

    const float* xf = x + (size_t)f * VV * Cin;
    const int nch = Cin / KCH;

    for (int kc = 0; kc < nch; ++kc) {
        __syncthreads();
        // ---- fill activation chunk (4 z-slices incl halo, 8x8 each, 4 ch)
#pragma unroll
        for (int rep = 0; rep < 2; ++rep) {
            int j  = t + rep * 128;      // 0..255
            int lz = j >> 6;             // 0..3  (pz directly)
            int vy = (j >> 3) & 7;
            int vx = j & 7;
            int gz = zbase + lz - 1;
            float val[KCH];
            if ((unsigned)gz < 8u) {
                float4 r0 = *(const float4*)(xf + (size_t)(gz * 64 + vy * 8 + vx) * Cin + kc * KCH);
                val[0] = r0.x; val[1] = r0.y; val[2] = r0.z; val[3] = r0.w;
            } else {
#pragma unroll
                for (int kk = 0; kk < KCH; ++kk) val[kk] = 0.f;
            }
            int p = lz * 100 + (vy + 1) * 10 + (vx + 1);
#pragma unroll
            for (int kk = 0; kk < KCH; ++kk) xs[kk * 400 + p] = val[kk];
        }
        // ---- fill weight chunk: 27*4*64 floats = 1728 float4
        {
            float4* wd = (float4*)ws;
            for (int i = t; i < 1728; i += 128) {
                int o  = i >> 6;         // /64 (64 float4 per tap)
                int r  = i & 63;
                int kk = r >> 4;         // /16  (16 float4 per cin)
                int c4 = r & 15;
                wd[i] = *(const float4*)&w[((size_t)o * Cin + (kc * KCH + kk)) * Cout + co0 + c4 * 4];
            }
        }
        __syncthreads();

        const float4* ws4 = (const float4*)ws;
#pragma unroll 1
        for (int kk = 0; kk < KCH; ++kk) {
            const float*  xkk = xs + kk * 400;
            const float4* wk4 = ws4 + kk * 16 + cg * 2;
#pragma unroll 1
            for (int dz = 0; dz < 3; ++dz) {
#pragma unroll 1
                for (int dy = 0; dy < 3; ++dy) {
                    // 10-float halo row, 8B-aligned -> 5x LDS.64
                    const float2* rp2 = (const float2*)(xkk + (zl + dz) * 100 + (gy + dy) * 10);
                    float2 p0 = rp2[0], p1 = rp2[1], p2 = rp2[2], p3 = rp2[3], p4 = rp2[4];
                    unsigned long long rd[10];
                    rd[0] = dup_f32x2(p0.x); rd[1] = dup_f32x2(p0.y);
                    rd[2] = dup_f32x2(p1.x); rd[3] = dup_f32x2(p1.y);
                    rd[4] = dup_f32x2(p2.x); rd[5] = dup_f32x2(p2.y);
                    rd[6] = dup_f32x2(p3.x); rd[7] = dup_f32x2(p3.y);
                    rd[8] = dup_f32x2(p4.x); rd[9] = dup_f32x2(p4.y);
                    const float4* wo4 = wk4 + (size_t)(dz * 9 + dy * 3) * KCH * 16;
#pragma unroll
                    for (int dx = 0; dx < 3; ++dx) {
                        F4U2 b0, b1;
                        b0.f = wo4[(size_t)dx * KCH * 16];
                        b1.f = wo4[(size_t)dx * KCH * 16 + 1];
                        unsigned long long bp0 = b0.u[0], bp1 = b0.u[1];
                        unsigned long long bp2 = b1.u[0], bp3 = b1.u[1];
#pragma unroll
                        for (int j = 0; j < 8; ++j) {
                            unsigned long long a2 = rd[j + dx];
                            fma_f32x2(acc[j][0], a2, bp0);
                            fma_f32x2(acc[j][1], a2, bp1);
                            fma_f32x2(acc[j][2], a2, bp2);
                            fma_f32x2(acc[j][3], a2, bp3);
                        }
                    }
                }
            }
        }
    }

    // ---- epilogue: bias (+residual) (+gelu)
    int co = co0 + cg * 8;
    float bv[8];
#pragma unroll
    for (int c = 0; c < 8; ++c) bv[c] = bias[co + c];
#pragma unroll
    for (int j = 0; j < 8; ++j) {
        int vox = (zbase + zl) * 64 + gy * 8 + j;
        size_t oi = ((size_t)f * VV + vox) * Cout + co;
        float r[8];
#pragma unroll
        for (int c = 0; c < 4; ++c) {
            float lo, hi;
            unpack_f32x2(acc[j][c], lo, hi);
            r[2 * c]     = lo + bv[2 * c];
            r[2 * c + 1] = hi + bv[2 * c + 1];
        }
        if (residual) {
            const float4* rp = (const float4*)(residual + oi);
            float4 r0 = rp[0], r1 = rp[1];
            r[0] += r0.x; r[1] += r0.y; r[2] += r0.z; r[3] += r0.w;
            r[4] += r1.x; r[5] += r1.y; r[6] += r1.z; r[7] += r1.w;
        }
        if (do_gelu) {
#pragma unroll
            for (int c = 0; c < 8; ++c)
                r[c] = 0.5f * r[c] * (1.f + erff(r[c] * 0.7071067811865475f));
        }
        float4* op = (float4*)(y + oi);
        op[0] = make_float4(r[0], r[1], r[2], r[3]);
        op[1] = make_float4(r[4], r[5], r[6], r[7]);
    }
}

// ---------------------------------------------------------------------------
// Attention over time (20 steps) per (b, voxel, head). One warp per unit.
// ---------------------------------------------------------------------------
__global__ void __launch_bounds__(128)
attn_kernel(const float* __restrict__ q, const float* __restrict__ k,
            const float* __restrict__ v, float* __restrict__ o)
{
    __shared__ float sm[4][2380];   // per warp: q 20x33, k 20x33, v 20x33, at 20x20
    int wlocal = threadIdx.x >> 5;
    int lane   = threadIdx.x & 31;
    int wid    = blockIdx.x * 4 + wlocal;     // 0..16383 (B*V*NH)
    int h  = wid & 7;
    int vx = (wid >> 3) & 511;
    int b  = wid >> 12;

    float* qs = sm[wlocal];
    float* ks = qs + 660;
    float* vs = ks + 660;
    float* at = vs + 660;

    size_t base = (size_t)vx * EE + h * HEADD + lane;
#pragma unroll
    for (int s = 0; s < SS; ++s) {
        size_t gi = (size_t)(b * SS + s) * (VV * EE) + base;
        qs[s * 33 + lane] = q[gi];
        ks[s * 33 + lane] = k[gi];
        vs[s * 33 + lane] = v[gi];
    }
    __syncwarp();

    const float scale = 0.17677669529663687f;  // 1/sqrt(32)
    int tt = lane;
#pragma unroll 1
    for (int s = 0; s < SS; ++s) {
        float sc = -1e30f;
        if (tt < SS) {
            float a = 0.f;
#pragma unroll
            for (int d = 0; d < HEADD; ++d)
                a = fmaf(qs[s * 33 + d], ks[tt * 33 + d], a);
            sc = a * scale;
        }
        float m = sc;
#pragma unroll
        for (int off = 16; off > 0; off >>= 1)
            m = fmaxf(m, __shfl_xor_sync(0xffffffffu, m, off));
        float e = (tt < SS) ? expf(sc - m) : 0.f;
        float su = e;
#pragma unroll
        for (int off = 16; off > 0; off >>= 1)
            su += __shfl_xor_sync(0xffffffffu, su, off);
        if (tt < SS) at[s * SS + tt] = e / su;
    }
    __syncwarp();

#pragma unroll 1
    for (int s = 0; s < SS; ++s) {
        float a = 0.f;
#pragma unroll
        for (int t2 = 0; t2 < SS; ++t2)
            a = fmaf(at[s * SS + t2], vs[t2 * 33 + lane], a);
        o[(size_t)(b * SS + s) * (VV * EE) + base] = a;
    }
}

// ---------------------------------------------------------------------------
// Final linear: [40960 x 256] @ [256 x 512] + bias -> logits
// ---------------------------------------------------------------------------
__global__ void __launch_bounds__(256)
linear_kernel(const float* __restrict__ A, const float* __restrict__ Bw,
              const float* __restrict__ bias, float* __restrict__ C)
{
    __shared__ float As[32 * 65];
    __shared__ float Bs[32 * 64];
    int t  = threadIdx.x;
    int tx = t & 15, ty = t >> 4;
    int m0 = blockIdx.x * 64, n0 = blockIdx.y * 64;
    float acc[4][4];
#pragma unroll
    for (int i = 0; i < 4; ++i)
#pragma unroll
        for (int j = 0; j < 4; ++j) acc[i][j] = 0.f;

    for (int kt = 0; kt < 8; ++kt) {
        for (int i = t; i < 2048; i += 256) {
            int r = i >> 5, kk = i & 31;
            As[kk * 65 + r] = A[(size_t)(m0 + r) * EE + kt * 32 + kk];
        }
        for (int i = t; i < 2048; i += 256) {
            int kk = i >> 6, c = i & 63;
            Bs[kk * 64 + c] = Bw[(size_t)(kt * 32 + kk) * NEE + n0 + c];
        }
        __syncthreads();
#pragma unroll
        for (int kk = 0; kk < 32; ++kk) {
            float a[4];
#pragma unroll
            for (int i = 0; i < 4; ++i) a[i] = As[kk * 65 + ty * 4 + i];
            float4 bvv = *(const float4*)&Bs[kk * 64 + tx * 4];
            float bvals[4] = {bvv.x, bvv.y, bvv.z, bvv.w};
#pragma unroll
            for (int i = 0; i < 4; ++i)
#pragma unroll
                for (int j = 0; j < 4; ++j)
                    acc[i][j] = fmaf(a[i], bvals[j], acc[i][j]);
        }
        __syncthreads();
    }
#pragma unroll
    for (int i = 0; i < 4; ++i)
#pragma unroll
        for (int j = 0; j < 4; ++j)
            C[(size_t)(m0 + ty * 4 + i) * NEE + n0 + tx * 4 + j] =
                acc[i][j] + bias[n0 + tx * 4 + j];
}

// ---------------------------------------------------------------------------
// Score transpose: score[b][c][p][v] = logits[b*20+16+p][v][c]
// ---------------------------------------------------------------------------
__global__ void score_kernel(const float* __restrict__ logits, float* __restrict__ out,
                             int out_size)
{
    __shared__ float tile[32][33];
    int bp = blockIdx.z;
    int b = bp >> 2, p = bp & 3;
    int v0 = blockIdx.x * 32, c0 = blockIdx.y * 32;
    int f = b * SS + BPTT + p;
    int t = threadIdx.x;
    int ci = t & 31, vi = t >> 5;     // vi 0..7
#pragma unroll
    for (int r = 0; r < 32; r += 8)
        tile[vi + r][ci] = logits[((size_t)f * VV + v0 + vi + r) * NEE + c0 + ci];
    __syncthreads();
    int vv2 = t & 31, cc = t >> 5;
#pragma unroll
    for (int r = 0; r < 32; r += 8) {
        size_t oidx = (((size_t)(b * NEE + c0 + cc + r)) * PRED + p) * VV + v0 + vv2;
        if (oidx < (size_t)out_size) out[oidx] = tile[vv2][cc + r];
    }
}

// ---------------------------------------------------------------------------
// Per-row log-softmax target loss + argmax. Warp per (b,p,v) row.
// ---------------------------------------------------------------------------
__global__ void loss_argmax_kernel(const float* __restrict__ logits,
                                   const int* __restrict__ ncode,
                                   float* __restrict__ rowloss,
                                   float* __restrict__ out, int write_code)
{
    int wid  = (int)((blockIdx.x * blockDim.x + threadIdx.x) >> 5);
    int lane = threadIdx.x & 31;
    if (wid >= NROWS) return;
    int v = wid & 511, p = (wid >> 9) & 3, b = wid >> 11;
    const float* lp = logits + ((size_t)(b * SS + BPTT + p) * VV + v) * NEE;

    float vals[16];
    float mx = -1e30f;
    int mi = 0;
#pragma unroll
    for (int i = 0; i < 16; ++i) {
        int c = lane + i * 32;
        float xv = lp[c];
        vals[i] = xv;
        if (xv > mx) { mx = xv; mi = c; }
    }
#pragma unroll
    for (int off = 16; off > 0; off >>= 1) {
        float om = __shfl_xor_sync(0xffffffffu, mx, off);
        int   oi = __shfl_xor_sync(0xffffffffu, mi, off);
        if (om > mx || (om == mx && oi < mi)) { mx = om; mi = oi; }
    }
    float se = 0.f;
#pragma unroll
    for (int i = 0; i < 16; ++i) se += expf(vals[i] - mx);
#pragma unroll
    for (int off = 16; off > 0; off >>= 1)
        se += __shfl_xor_sync(0xffffffffu, se, off);

    int tgt = ncode[wid];
    if (lane == (tgt & 31))
        rowloss[wid] = -(vals[tgt >> 5] - mx - logf(se));
    if (write_code && lane == 0)
        out[(size_t)SCORE_SIZE + 1 + wid] = (float)mi;
}

__global__ void loss_reduce_kernel(const float* __restrict__ rowloss,
                                   float* __restrict__ out, int loss_off)
{
    __shared__ float smr[256];
    int t = threadIdx.x;
    float a = 0.f;
    for (int i = t; i < NROWS; i += 256) a += rowloss[i];
    smr[t] = a;
    __syncthreads();
    for (int s = 128; s > 0; s >>= 1) {
        if (t < s) smr[t] += smr[t + s];
        __syncthreads();
    }
    if (t == 0) out[loss_off] = smr[0] * (1.f / (float)NROWS);
}

// ---------------------------------------------------------------------------
// Orchestration
// ---------------------------------------------------------------------------
extern "C" void kernel_launch(void* const* d_in, const int* in_sizes, int n_in,
                              void* d_out, int out_size)
{
    (void)in_sizes; (void)n_in;
    const int*   code   = (const int*)  d_in[0];
    const int*   ncode  = (const int*)  d_in[1];
    const float* emb    = (const float*)d_in[2];
    const float* pos    = (const float*)d_in[3];
    const float* ln1s   = (const float*)d_in[4];
    const float* ln1b   = (const float*)d_in[5];
    const float* ln2s   = (const float*)d_in[6];
    const float* ln2b   = (const float*)d_in[7];
    const float* wq     = (const float*)d_in[8];
    const float* bq     = (const float*)d_in[9];
    const float* wk     = (const float*)d_in[10];
    const float* bk     = (const float*)d_in[11];
    const float* wv     = (const float*)d_in[12];
    const float* bv     = (const float*)d_in[13];
    const float* wo     = (const float*)d_in[14];
    const float* bo     = (const float*)d_in[15];
    const float* w1     = (const float*)d_in[16];
    const float* b1     = (const float*)d_in[17];
    const float* w2     = (const float*)d_in[18];
    const float* b2     = (const float*)d_in[19];
    const float* lnfs   = (const float*)d_in[20];
    const float* lnfb   = (const float*)d_in[21];
    const float* decw   = (const float*)d_in[22];
    const float* decb   = (const float*)d_in[23];
    const float* declns = (const float*)d_in[24];
    const float* declnb = (const float*)d_in[25];
    const float* linw   = (const float*)d_in[26];
    const float* linb   = (const float*)d_in[27];
    float* out = (float*)d_out;

    float *px, *ph, *pq, *pk, *pv, *pa, *phid, *plog, *prl;
    cudaGetSymbolAddress((void**)&px,   g_x);
    cudaGetSymbolAddress((void**)&ph,   g_h);
    cudaGetSymbolAddress((void**)&pq,   g_q);
    cudaGetSymbolAddress((void**)&pk,   g_k);
    cudaGetSymbolAddress((void**)&pv,   g_v);
    cudaGetSymbolAddress((void**)&pa,   g_ao);
    cudaGetSymbolAddress((void**)&phid, g_hid);
    cudaGetSymbolAddress((void**)&plog, g_logits);
    cudaGetSymbolAddress((void**)&prl,  g_rowloss);

    cudaFuncSetAttribute(conv3d_kernel,
                         cudaFuncAttributeMaxDynamicSharedMemorySize,
                         CONV_SMEM_BYTES);

    const int ROWS = FF * VV;                  // 40960
    const int LN_BLOCKS = (ROWS * 32) / 256;   // 5120
    const size_t WEE = 27 * 256 * 256;         // per-layer E->E weight stride
    const size_t WEH = 27 * 256 * 512;         // per-layer E->HID (== HID->E)

    embed_kernel<<<(int)((FVE + 255) / 256), 256>>>(code, emb, pos, px);

    dim3 cgE(FF, 4, 4);   // Cout=256
    dim3 cgH(FF, 8, 4);   // Cout=512
    for (int i = 0; i < 4; ++i) {
        ln_kernel<<<LN_BLOCKS, 256>>>(px, ph, ln1s + i * EE, ln1b + i * EE, ROWS);
        conv3d_kernel<<<cgE, 128, CONV_SMEM_BYTES>>>(ph, wq + i * WEE, bq + i * EE, nullptr, pq, 256, 256, 0);
        conv3d_kernel<<<cgE, 128, CONV_SMEM_BYTES>>>(ph, wk + i * WEE, bk + i * EE, nullptr, pk, 256, 256, 0);
        conv3d_kernel<<<cgE, 128, CONV_SMEM_BYTES>>>(ph, wv + i * WEE, bv + i * EE, nullptr, pv, 256, 256, 0);
        attn_kernel<<<4096, 128>>>(pq, pk, pv, pa);
        conv3d_kernel<<<cgE, 128, CONV_SMEM_BYTES>>>(pa, wo + i * WEE, bo + i * EE, px, px, 256, 256, 0);
        ln_kernel<<<LN_BLOCKS, 256>>>(px, ph, ln2s + i * EE, ln2b + i * EE, ROWS);
        conv3d_kernel<<<cgH, 128, CONV_SMEM_BYTES>>>(ph, w1 + i * WEH, b1 + i * HIDD, nullptr, phid, 256, 512, 1);
        conv3d_kernel<<<cgE, 128, CONV_SMEM_BYTES>>>(phid, w2 + i * WEH, b2 + i * EE, px, px, 512, 256, 0);
    }

    ln_kernel<<<LN_BLOCKS, 256>>>(px, ph, lnfs, lnfb, ROWS);
    conv3d_kernel<<<cgE, 128, CONV_SMEM_BYTES>>>(ph, decw, decb, nullptr, pq, 256, 256, 1);
    ln_kernel<<<LN_BLOCKS, 256>>>(pq, pk, declns, declnb, ROWS);
    linear_kernel<<<dim3(ROWS / 64, NEE / 64), 256>>>(pk, linw, linb, plog);

    if (out_size >= SCORE_SIZE) {
        dim3 sg(16, 16, 16);
        score_kernel<<<sg, 256>>>(plog, out, out_size);
    }
    int write_code = (out_size >= SCORE_SIZE + 1 + NROWS) ? 1 : 0;
    loss_argmax_kernel<<<(NROWS * 32) / 256, 256>>>(plog, ncode, prl, out, write_code);

    int loss_off = -1;
    if (out_size == 1) loss_off = 0;
    else if (out_size > SCORE_SIZE) loss_off = SCORE_SIZE;
    if (loss_off >= 0)
        loss_reduce_kernel<<<1, 256>>>(prl, out, loss_off);
}